// round 17
// baseline (speedup 1.0000x reference)
#include <cuda_runtime.h>
#include <cuda_bf16.h>
#include <cuda_fp16.h>
#include <cstdint>
#include <math.h>

#define BB 8
#define NN 2048
#define DD 768

typedef __nv_bfloat16 bf16;

// ---------------- scratch (no allocation allowed) ----------------
__device__ bf16 g_K2h[BB * NN * DD];   // row-softmax(x2)  [n][d] bf16
__device__ bf16 g_E2h[BB * NN * DD];   // exp(x2)          [n][d] bf16
__device__ bf16 g_K3h[BB * NN * DD];
__device__ bf16 g_E3h[BB * NN * DD];
__device__ uint8_t g_Kt2[BB * NN * DD];  // 256*K' fp8 e4m3 [d][n]
__device__ uint8_t g_Et2[BB * NN * DD];  // E fp8 e4m3      [d][n]
__device__ uint8_t g_Kt3[BB * NN * DD];
__device__ uint8_t g_Et3[BB * NN * DD];
__device__ float g_c2i[BB * DD];       // 1 / (256 * colsum(E_fp8))
__device__ float g_c3i[BB * DD];
__device__ bf16 g_S1h[BB * DD * DD];
__device__ bf16 g_S2h[BB * DD * DD];
__device__ bf16 g_MTh[BB * DD * DD];
__device__ bf16 g_Wh [2 * DD * DD];
__device__ bf16 g_xh [BB * NN * DD];

// ---------------- helpers ----------------
__device__ __forceinline__ uint32_t smem_u32(const void* p) {
    uint32_t a;
    asm("{ .reg .u64 t; cvta.to.shared.u64 t, %1; cvt.u32.u64 %0, t; }" : "=r"(a) : "l"(p));
    return a;
}
__device__ __forceinline__ void ldsm4(uint32_t* r, uint32_t addr) {
    asm volatile("ldmatrix.sync.aligned.m8n8.x4.shared.b16 {%0,%1,%2,%3}, [%4];"
        : "=r"(r[0]), "=r"(r[1]), "=r"(r[2]), "=r"(r[3]) : "r"(addr));
}
__device__ __forceinline__ void mma16816(float* d, const uint32_t* a, const uint32_t* b) {
    asm volatile("mma.sync.aligned.m16n8k16.row.col.f32.bf16.bf16.f32 "
        "{%0,%1,%2,%3}, {%4,%5,%6,%7}, {%8,%9}, {%0,%1,%2,%3};"
        : "+f"(d[0]), "+f"(d[1]), "+f"(d[2]), "+f"(d[3])
        : "r"(a[0]), "r"(a[1]), "r"(a[2]), "r"(a[3]), "r"(b[0]), "r"(b[1]));
}
__device__ __forceinline__ void mma_fp8(float* d, const uint32_t* a, const uint32_t* b) {
    asm volatile("mma.sync.aligned.m16n8k32.row.col.f32.e4m3.e4m3.f32 "
        "{%0,%1,%2,%3}, {%4,%5,%6,%7}, {%8,%9}, {%0,%1,%2,%3};"
        : "+f"(d[0]), "+f"(d[1]), "+f"(d[2]), "+f"(d[3])
        : "r"(a[0]), "r"(a[1]), "r"(a[2]), "r"(a[3]), "r"(b[0]), "r"(b[1]));
}
__device__ __forceinline__ void cpa16(uint32_t dst, const void* src) {
    asm volatile("cp.async.cg.shared.global [%0], [%1], 16;" :: "r"(dst), "l"(src));
}
#define CP_COMMIT() asm volatile("cp.async.commit_group;" ::: "memory")

__device__ __forceinline__ uint32_t pack_bf2(float a, float b) {
    return (uint32_t)__bfloat16_as_ushort(__float2bfloat16_rn(a)) |
           ((uint32_t)__bfloat16_as_ushort(__float2bfloat16_rn(b)) << 16);
}

// FMA-pipe exp (no MUFU)
__device__ __forceinline__ float fexp(float x) {
    const float L2E = 1.4426950408889634f;
    const float MAGIC = 12582912.0f;
    float y = x * L2E;
    float t = y + MAGIC;
    float r = t - MAGIC;
    float f = y - r;
    float p = 1.3333558146e-3f;
    p = fmaf(p, f, 9.6181291076e-3f);
    p = fmaf(p, f, 5.5504108664e-2f);
    p = fmaf(p, f, 2.4022650696e-1f);
    p = fmaf(p, f, 6.9314718056e-1f);
    p = fmaf(p, f, 1.0f);
    int j = (__float_as_int(t) - 0x4B400000 + 127) << 23;
    return p * __int_as_float(j);
}

// ---------------------------------------------------------------------------
// Row exp kernel: E = exp(v) (bf16) and K' = exp(v)/rowsum (bf16). [n][d]
// ---------------------------------------------------------------------------
__global__ void rowexp2_k(const float* __restrict__ in2, bf16* __restrict__ k2, bf16* __restrict__ e2,
                          const float* __restrict__ in3, bf16* __restrict__ k3, bf16* __restrict__ e3) {
    int gw = blockIdx.x * 8 + (threadIdx.x >> 5);
    int lane = threadIdx.x & 31;
    const int nrows = BB * NN;
    const float* in = (gw < nrows) ? in2 : in3;
    bf16* ko = (gw < nrows) ? k2 : k3;
    bf16* eo = (gw < nrows) ? e2 : e3;
    int row = (gw < nrows) ? gw : gw - nrows;

    const float* p = in + (size_t)row * DD;
    float e[6][4];
    float s = 0.0f;
    #pragma unroll
    for (int j = 0; j < 6; j++) {
        float4 v = *(const float4*)(p + (j * 32 + lane) * 4);
        e[j][0] = fexp(v.x); e[j][1] = fexp(v.y);
        e[j][2] = fexp(v.z); e[j][3] = fexp(v.w);
        s += (e[j][0] + e[j][1]) + (e[j][2] + e[j][3]);
    }
    #pragma unroll
    for (int off = 16; off; off >>= 1)
        s += __shfl_xor_sync(0xffffffffu, s, off);
    float inv = 1.0f / s;

    bf16* kp = ko + (size_t)row * DD;
    bf16* ep = eo + (size_t)row * DD;
    #pragma unroll
    for (int j = 0; j < 6; j++) {
        uint2 we = make_uint2(pack_bf2(e[j][0], e[j][1]), pack_bf2(e[j][2], e[j][3]));
        uint2 wk = make_uint2(pack_bf2(e[j][0] * inv, e[j][1] * inv),
                              pack_bf2(e[j][2] * inv, e[j][3] * inv));
        *(uint2*)(ep + (j * 32 + lane) * 4) = we;
        *(uint2*)(kp + (j * 32 + lane) * 4) = wk;
    }
}

// ---------------------------------------------------------------------------
// Transpose + fp8 convert: bf16 [b][n][d] -> e4m3 [b][d][n], K planes x256.
// grid (NN/32, DD/32, 4*BB), 256 threads.
// ---------------------------------------------------------------------------
__global__ void transpose_fp8_k(const bf16* __restrict__ K2, const bf16* __restrict__ E2,
                                const bf16* __restrict__ K3, const bf16* __restrict__ E3,
                                uint8_t* __restrict__ Kt2, uint8_t* __restrict__ Et2,
                                uint8_t* __restrict__ Kt3, uint8_t* __restrict__ Et3) {
    int z = blockIdx.z;
    int pl = z >> 3, b = z & 7;
    const bf16* in;
    uint8_t* out;
    float sc;
    if (pl == 0)      { in = K2; out = Kt2; sc = 256.0f; }
    else if (pl == 1) { in = E2; out = Et2; sc = 1.0f; }
    else if (pl == 2) { in = K3; out = Kt3; sc = 256.0f; }
    else              { in = E3; out = Et3; sc = 1.0f; }
    in  += (size_t)b * NN * DD;
    out += (size_t)b * NN * DD;

    int n0 = blockIdx.x * 32, d0 = blockIdx.y * 32;
    __shared__ float t[32][33];
    int tx = threadIdx.x & 31, ty = threadIdx.x >> 5;
    #pragma unroll
    for (int i = ty; i < 32; i += 8)
        t[i][tx] = __bfloat162float(in[(size_t)(n0 + i) * DD + d0 + tx]) * sc;
    __syncthreads();

    int d = threadIdx.x >> 3;          // 0..31
    int nq = (threadIdx.x & 7) * 4;    // 0,4,...,28
    uint16_t u0, u1;
    asm("cvt.rn.satfinite.e4m3x2.f32 %0, %1, %2;" : "=h"(u0)
        : "f"(t[nq + 1][d]), "f"(t[nq][d]));
    asm("cvt.rn.satfinite.e4m3x2.f32 %0, %1, %2;" : "=h"(u1)
        : "f"(t[nq + 3][d]), "f"(t[nq + 2][d]));
    *(uint32_t*)(out + (size_t)(d0 + d) * NN + n0 + nq) =
        (uint32_t)u0 | ((uint32_t)u1 << 16);
}

// ---------------------------------------------------------------------------
// Row-reduce of fp8 Et [d=e][n] -> 1/(256*sum). Warp per (e,b). grid (DD/8,BB,2)
// ---------------------------------------------------------------------------
__global__ void colsum_fp8_k(const uint8_t* __restrict__ Et2, float* __restrict__ c2i,
                             const uint8_t* __restrict__ Et3, float* __restrict__ c3i) {
    const uint8_t* E = blockIdx.z ? Et3 : Et2;
    float* ci = blockIdx.z ? c3i : c2i;
    int e = blockIdx.x * 8 + (threadIdx.x >> 5);
    int b = blockIdx.y;
    int lane = threadIdx.x & 31;
    const uint8_t* row = E + (size_t)b * NN * DD + (size_t)e * NN;

    float s = 0.0f;
    #pragma unroll
    for (int j = 0; j < 4; j++) {
        uint4 v = *(const uint4*)(row + lane * 16 + j * 512);
        uint32_t ws[4] = {v.x, v.y, v.z, v.w};
        #pragma unroll
        for (int k = 0; k < 4; k++) {
            #pragma unroll
            for (int h = 0; h < 2; h++) {
                uint16_t u = (uint16_t)(ws[k] >> (h * 16));
                uint32_t h2;
                asm("cvt.rn.f16x2.e4m3x2 %0, %1;" : "=r"(h2) : "h"(u));
                __half2 hh = *(__half2*)&h2;
                s += __low2float(hh) + __high2float(hh);
            }
        }
    }
    #pragma unroll
    for (int off = 16; off; off >>= 1)
        s += __shfl_xor_sync(0xffffffffu, s, off);
    if (lane == 0) ci[(size_t)b * DD + e] = 1.0f / (256.0f * s);
}

// ---------------------------------------------------------------------------
// Fused fp32 -> bf16 cast of W1, W2, x (side stream)
// ---------------------------------------------------------------------------
#define W4 (DD * DD / 4)
#define X4 (BB * NN * DD / 4)
__global__ void cast_all_k(const float* __restrict__ W1, const float* __restrict__ W2,
                           const float* __restrict__ x,
                           bf16* __restrict__ Wh, bf16* __restrict__ xh) {
    int i = blockIdx.x * blockDim.x + threadIdx.x;
    const float* src;
    bf16* dst;
    int j;
    if (i < W4)            { src = W1; dst = Wh;                 j = i; }
    else if (i < 2 * W4)   { src = W2; dst = Wh + (size_t)DD*DD; j = i - W4; }
    else if (i < 2*W4+X4)  { src = x;  dst = xh;                 j = i - 2 * W4; }
    else return;
    float4 v = ((const float4*)src)[j];
    ((uint2*)dst)[j] = make_uint2(pack_bf2(v.x, v.y), pack_bf2(v.z, v.w));
}

#define ATILE  16384
#define STAGE  (2 * ATILE)
#define NSTG   3
#define SMEMSZ (NSTG * STAGE)

// ---------------------------------------------------------------------------
// fp8 GEMM (attention): S[d][e] = (sum_n 256K'[d][n] * E[e][n]) * cinv[e]
// CTA 128x128, K-TILE 128 tokens (16 iters), 8 warps, cp.async NSTG=3.
// z: 0-7 tensor2 batch, 8-15 tensor3 batch.
// ---------------------------------------------------------------------------
__global__ __launch_bounds__(256, 2)
void gemm_fp8_k(const uint8_t* __restrict__ Kt2, const uint8_t* __restrict__ Et2,
                const uint8_t* __restrict__ Kt3, const uint8_t* __restrict__ Et3,
                const float* __restrict__ c2i, const float* __restrict__ c3i,
                bf16* __restrict__ S1, bf16* __restrict__ S2)
{
    extern __shared__ char sm[];
    uint32_t smb = smem_u32(sm);
    int tid = threadIdx.x, lane = tid & 31, wid = tid >> 5;
    int z = blockIdx.z;
    int b = z & 7;
    const uint8_t* Ap = (z < 8) ? Kt2 : Kt3;
    const uint8_t* Bp = (z < 8) ? Et2 : Et3;
    const float* cinvp = (z < 8) ? c2i : c3i;
    bf16* Sp = (z < 8) ? S1 : S2;
    int n0 = blockIdx.x * 128, m0 = blockIdx.y * 128;
    int wm = wid & 3, wn = wid >> 2;

    const uint8_t* Ab = Ap + (size_t)b * NN * DD + (size_t)m0 * NN;
    const uint8_t* Bb = Bp + (size_t)b * NN * DD + (size_t)n0 * NN;
    const int KT = NN / 128;   // 16

    #define ISSUE_F8(s) do {                                                             \
        int _s = (s);                                                                    \
        uint32_t sb = smb + (uint32_t)((_s % NSTG)) * STAGE;                             \
        int ko = _s * 128;                                                               \
        _Pragma("unroll")                                                                \
        for (int j = 0; j < 4; j++) {                                                    \
            int q = tid + 256 * j;                                                       \
            int r = q >> 3, c = q & 7;                                                   \
            uint32_t d = (uint32_t)r * 128 + ((uint32_t)(c ^ (r & 7)) << 4);             \
            cpa16(sb + d,         Ab + (size_t)r * NN + ko + c * 16);                    \
            cpa16(sb + ATILE + d, Bb + (size_t)r * NN + ko + c * 16);                    \
        }                                                                                \
        CP_COMMIT();                                                                     \
    } while (0)

    int rA  = wm * 32 + (lane & 7) + ((lane >> 3) & 1) * 8;
    int cAq = lane >> 4;
    int swA = rA & 7;
    int rB  = wn * 64 + (lane & 7) + ((lane >> 4) & 1) * 8;
    int cBq = (lane >> 3) & 1;
    int swB = rB & 7;

    float acc[2][8][4] = {};

    ISSUE_F8(0);
    ISSUE_F8(1);

    for (int kt = 0; kt < KT; kt++) {
        if (kt == KT - 1) asm volatile("cp.async.wait_group 0;" ::: "memory");
        else              asm volatile("cp.async.wait_group 1;" ::: "memory");
        __syncthreads();
        if (kt + 2 < KT) ISSUE_F8(kt + 2);

        uint32_t bA = smb + (uint32_t)(kt % NSTG) * STAGE;
        uint32_t bB = bA + ATILE;
        #pragma unroll
        for (int ks = 0; ks < 4; ks++) {          // 4 x k32 = 128 tokens
            uint32_t aH[2][4], bH[4][4];
            uint32_t offA = (uint32_t)rA * 128 + (uint32_t)(((ks * 2 + cAq) ^ swA) << 4);
            #pragma unroll
            for (int mi = 0; mi < 2; mi++)
                ldsm4(aH[mi], bA + offA + mi * 2048);
            uint32_t offB = (uint32_t)rB * 128 + (uint32_t)(((ks * 2 + cBq) ^ swB) << 4);
            #pragma unroll
            for (int np = 0; np < 4; np++)
                ldsm4(bH[np], bB + offB + np * 2048);
            #pragma unroll
            for (int mi = 0; mi < 2; mi++)
                #pragma unroll
                for (int ni = 0; ni < 8; ni++)
                    mma_fp8(acc[mi][ni], aH[mi], &bH[ni >> 1][(ni & 1) * 2]);
        }
    }

    int g = lane >> 2, t4 = lane & 3;
    #pragma unroll
    for (int mi = 0; mi < 2; mi++) {
        #pragma unroll
        for (int ni = 0; ni < 8; ni++) {
            int row0 = m0 + wm * 32 + mi * 16 + g;
            int col = n0 + wn * 64 + ni * 8 + t4 * 2;
            float cs0 = cinvp[(size_t)b * DD + col];
            float cs1 = cinvp[(size_t)b * DD + col + 1];
            size_t i0 = (size_t)b * DD * DD + (size_t)row0 * DD + col;
            size_t i1 = i0 + (size_t)8 * DD;
            *(uint32_t*)(Sp + i0) = pack_bf2(acc[mi][ni][0] * cs0, acc[mi][ni][1] * cs1);
            *(uint32_t*)(Sp + i1) = pack_bf2(acc[mi][ni][2] * cs0, acc[mi][ni][3] * cs1);
        }
    }
    #undef ISSUE_F8
}

// ---------------------------------------------------------------------------
// bf16 GEMM (R11 core, non-TR only): C[m][n] = sum_k A[m][k] * B[n][k]
// mode 0: C -> bf16. mode 1: fp32 out = f*(acc+bias)+x.
// ---------------------------------------------------------------------------
__global__ __launch_bounds__(256, 2)
void gemm1t_k(const bf16* __restrict__ Ah1, const bf16* __restrict__ Bh1, int kt1,
              const bf16* __restrict__ Ah2, const bf16* __restrict__ Bh2, int kt2,
              long sA1, long sB1, long sA2, long sB2,
              int lda1, int ldb1, int lda2, int ldb2,
              int mode,
              float* __restrict__ Cf, bf16* __restrict__ Ch,
              long sC, int ldc,
              const float* __restrict__ bias1, const float* __restrict__ bias2,
              const float* __restrict__ gate, const float* __restrict__ xres)
{
    extern __shared__ char sm[];
    uint32_t smb = smem_u32(sm);
    int tid = threadIdx.x, lane = tid & 31, wid = tid >> 5;
    int b = blockIdx.z, n0 = blockIdx.x * 128, m0 = blockIdx.y * 128;
    int wm = wid & 3, wn = wid >> 2;

    const bf16* Ab1 = Ah1 + (size_t)b * sA1 + (size_t)m0 * lda1;
    const bf16* Bb1 = Bh1 + (size_t)b * sB1 + (size_t)n0 * ldb1;
    const bf16* Ab2 = Ah2 ? Ah2 + (size_t)b * sA2 + (size_t)m0 * lda2 : (const bf16*)0;
    const bf16* Bb2 = Bh2 ? Bh2 + (size_t)b * sB2 + (size_t)n0 * ldb2 : (const bf16*)0;
    int KT = kt1 + kt2;

    #define ISSUE_STAGE(s) do {                                                          \
        int _s = (s);                                                                    \
        const bf16 *ah, *bh; int la, lb;                                                 \
        if (_s < kt1) { ah = Ab1; bh = Bb1; la = lda1; lb = ldb1; }                      \
        else { ah = Ab2; bh = Bb2; la = lda2; lb = ldb2; _s -= kt1; }                    \
        uint32_t sb = smb + (uint32_t)(((s) % NSTG)) * STAGE;                            \
        int ko = _s * 64;                                                                \
        _Pragma("unroll")                                                                \
        for (int j = 0; j < 4; j++) {                                                    \
            int q = tid + 256 * j;                                                       \
            int r = q >> 3, c = q & 7;                                                   \
            uint32_t d = (uint32_t)r * 128 + ((uint32_t)(c ^ (r & 7)) << 4);             \
            cpa16(sb + d,         ah + (size_t)r * la + ko + c * 8);                     \
            cpa16(sb + ATILE + d, bh + (size_t)r * lb + ko + c * 8);                     \
        }                                                                                \
        CP_COMMIT();                                                                     \
    } while (0)

    int rA  = wm * 32 + (lane & 7) + ((lane >> 3) & 1) * 8;
    int cAq = lane >> 4;
    int swA = rA & 7;
    int rB  = wn * 64 + (lane & 7) + ((lane >> 4) & 1) * 8;
    int cBq = (lane >> 3) & 1;
    int swB = rB & 7;

    float acc[2][8][4] = {};

    ISSUE_STAGE(0);
    ISSUE_STAGE(1);

    for (int kt = 0; kt < KT; kt++) {
        if (kt == KT - 1) asm volatile("cp.async.wait_group 0;" ::: "memory");
        else              asm volatile("cp.async.wait_group 1;" ::: "memory");
        __syncthreads();
        if (kt + 2 < KT) ISSUE_STAGE(kt + 2);

        uint32_t bA = smb + (uint32_t)(kt % NSTG) * STAGE;
        uint32_t bB = bA + ATILE;
        #pragma unroll
        for (int ks = 0; ks < 4; ks++) {
            uint32_t aH[2][4], bH[4][4];
            uint32_t offA = (uint32_t)rA * 128 + (uint32_t)(((ks * 2 + cAq) ^ swA) << 4);
            #pragma unroll
            for (int mi = 0; mi < 2; mi++)
                ldsm4(aH[mi], bA + offA + mi * 2048);
            uint32_t offB = (uint32_t)rB * 128 + (uint32_t)(((ks * 2 + cBq) ^ swB) << 4);
            #pragma unroll
            for (int np = 0; np < 4; np++)
                ldsm4(bH[np], bB + offB + np * 2048);
            #pragma unroll
            for (int mi = 0; mi < 2; mi++)
                #pragma unroll
                for (int ni = 0; ni < 8; ni++)
                    mma16816(acc[mi][ni], aH[mi], &bH[ni >> 1][(ni & 1) * 2]);
        }
    }

    int g = lane >> 2, t4 = lane & 3;
    float f = 0.0f;
    if (mode == 1) f = 1.0f / (1.0f + __expf(-gate[0]));

    #pragma unroll
    for (int mi = 0; mi < 2; mi++) {
        #pragma unroll
        for (int ni = 0; ni < 8; ni++) {
            int row0 = m0 + wm * 32 + mi * 16 + g;
            int col = n0 + wn * 64 + ni * 8 + t4 * 2;
            if (mode == 0) {
                size_t i0 = (size_t)b * sC + (size_t)row0 * ldc + col;
                size_t i1 = i0 + (size_t)8 * ldc;
                *(uint32_t*)(Ch + i0) = pack_bf2(acc[mi][ni][0], acc[mi][ni][1]);
                *(uint32_t*)(Ch + i1) = pack_bf2(acc[mi][ni][2], acc[mi][ni][3]);
            } else {
                float g1 = bias1[col] + bias2[col];
                float g2 = bias1[col + 1] + bias2[col + 1];
                const float* x0 = xres + (size_t)b * NN * DD + (size_t)row0 * DD + col;
                const float* x1 = x0 + (size_t)8 * DD;
                float2 xv0 = *(const float2*)x0;
                float2 xv1 = *(const float2*)x1;
                float* p0 = Cf + (size_t)b * sC + (size_t)row0 * ldc + col;
                float* p1 = p0 + (size_t)8 * ldc;
                *(float2*)p0 = make_float2(f * (acc[mi][ni][0] + g1) + xv0.x,
                                           f * (acc[mi][ni][1] + g2) + xv0.y);
                *(float2*)p1 = make_float2(f * (acc[mi][ni][2] + g1) + xv1.x,
                                           f * (acc[mi][ni][3] + g2) + xv1.y);
            }
        }
    }
    #undef ISSUE_STAGE
}

// ---------------------------------------------------------------------------
extern "C" void kernel_launch(void* const* d_in, const int* in_sizes, int n_in,
                              void* d_out, int out_size) {
    const float* x  = (const float*)d_in[0];
    const float* x2 = (const float*)d_in[1];
    const float* x3 = (const float*)d_in[2];
    const float* W1 = (const float*)d_in[3];
    const float* b1 = (const float*)d_in[4];
    const float* W2 = (const float*)d_in[5];
    const float* b2 = (const float*)d_in[6];
    const float* w  = (const float*)d_in[7];
    float* out = (float*)d_out;

    bf16 *K2h, *E2h, *K3h, *E3h, *S1h, *S2h, *MTh, *Wh, *xh;
    uint8_t *Kt2, *Et2, *Kt3, *Et3;
    float *c2i, *c3i;
    cudaGetSymbolAddress((void**)&K2h, g_K2h);
    cudaGetSymbolAddress((void**)&E2h, g_E2h);
    cudaGetSymbolAddress((void**)&K3h, g_K3h);
    cudaGetSymbolAddress((void**)&E3h, g_E3h);
    cudaGetSymbolAddress((void**)&Kt2, g_Kt2);
    cudaGetSymbolAddress((void**)&Et2, g_Et2);
    cudaGetSymbolAddress((void**)&Kt3, g_Kt3);
    cudaGetSymbolAddress((void**)&Et3, g_Et3);
    cudaGetSymbolAddress((void**)&c2i, g_c2i);
    cudaGetSymbolAddress((void**)&c3i, g_c3i);
    cudaGetSymbolAddress((void**)&S1h, g_S1h);
    cudaGetSymbolAddress((void**)&S2h, g_S2h);
    cudaGetSymbolAddress((void**)&MTh, g_MTh);
    cudaGetSymbolAddress((void**)&Wh,  g_Wh);
    cudaGetSymbolAddress((void**)&xh,  g_xh);

    cudaFuncSetAttribute(gemm1t_k,  cudaFuncAttributeMaxDynamicSharedMemorySize, SMEMSZ);
    cudaFuncSetAttribute(gemm_fp8_k, cudaFuncAttributeMaxDynamicSharedMemorySize, SMEMSZ);

    static cudaStream_t s2 = nullptr;
    static cudaEvent_t evFork = nullptr, evJoin = nullptr;
    if (!s2) {
        cudaStreamCreateWithFlags(&s2, cudaStreamNonBlocking);
        cudaEventCreateWithFlags(&evFork, cudaEventDisableTiming);
        cudaEventCreateWithFlags(&evJoin, cudaEventDisableTiming);
    }

    long sTok = (long)NN * DD;
    long sDD  = (long)DD * DD;

    // 1) fork: fused bf16 casts (W1, W2, x) on side stream
    cudaEventRecord(evFork, 0);
    cudaStreamWaitEvent(s2, evFork, 0);
    cast_all_k<<<(2 * W4 + X4 + 255) / 256, 256, 0, s2>>>(W1, W2, x, Wh, xh);
    cudaEventRecord(evJoin, s2);

    // 2) fused row softmax+exp: K' = exp/rowsum, E = exp (bf16, [n][d])
    rowexp2_k<<<2 * BB * NN / 8, 256>>>(x2, K2h, E2h, x3, K3h, E3h);

    // 3) transpose + fp8 convert: Kt = 256K' [d][n], Et = E [d][n]
    transpose_fp8_k<<<dim3(NN / 32, DD / 32, 4 * BB), 256>>>(
        K2h, E2h, K3h, E3h, Kt2, Et2, Kt3, Et3);

    // 4) 1/(256*colsum) from fp8 Et rows
    colsum_fp8_k<<<dim3(DD / 8, BB, 2), 256>>>(Et2, c2i, Et3, c3i);

    // 5) fp8 attention GEMMs: S = (256K'^T E)*(1/256c)  (16 z-blocks)
    gemm_fp8_k<<<dim3(DD / 128, DD / 128, 2 * BB), 256, SMEMSZ>>>(
        Kt2, Et2, Kt3, Et3, c2i, c3i, S1h, S2h);

    // join: GEMM6 needs Wh; GEMM7 needs xh
    cudaStreamWaitEvent(0, evJoin, 0);

    // 6) MT[e][d] = sum_k W1[e][k]*S1[d][k] + W2[e][k]*S2[d][k]
    gemm1t_k<<<dim3(DD / 128, DD / 128, BB), 256, SMEMSZ>>>(
        Wh, S1h, DD / 64, Wh + (size_t)DD * DD, S2h, DD / 64,
        0, sDD, 0, sDD, DD, DD, DD, DD,
        0, nullptr, MTh, sDD, DD,
        nullptr, nullptr, nullptr, nullptr);

    // 7) out[n][e] = f*( sum_d x[n][d]*MT[e][d] + b1[e]+b2[e] ) + x[n][e]
    gemm1t_k<<<dim3(DD / 128, NN / 128, BB), 256, SMEMSZ>>>(
        xh, MTh, DD / 64, nullptr, nullptr, 0,
        sTok, sDD, 0, 0, DD, DD, 0, 0,
        1, out, nullptr, sTok, DD,
        b1, b2, w, x);
}